// round 2
// baseline (speedup 1.0000x reference)
#include <cuda_runtime.h>
#include <cstdint>

// ---------------------------------------------------------------------------
// EquiAdapter fused pipeline, tf32 mma.sync version (round 1)
// Shapes: B=8, n_equi=4, T=1024, D_eq=1024, N_GROUP=8, BLOCKS=128,
//         T_text=64, d_llm=2048
// ---------------------------------------------------------------------------

#define NTOK   32768                 // B * n_equi * T
#define SCALE_F 0.08838834764831845f // 128^-0.5

// ------------------------- scratch (device globals) ------------------------
__device__ float g_k[512 * 128];        // [B*T_text, 128]
__device__ float g_v[512 * 128];
__device__ float g_inv[NTOK * 128];     // maxpooled invariant features
__device__ float g_q[NTOK * 128];
__device__ float g_ctx[NTOK * 128];
__device__ float g_gate[NTOK * 128];
__device__ float g_gamma[NTOK * 128];
__device__ float g_beta[NTOK * 128];

// ------------------------------ helpers ------------------------------------
__device__ __forceinline__ float rna_tf32(float x) {
    uint32_t r;
    asm("cvt.rna.tf32.f32 %0, %1;" : "=r"(r) : "f"(x));
    return __uint_as_float(r);
}

__device__ __forceinline__ void mma_tf32(float* d, const float* a, float b0, float b1) {
    asm volatile(
        "mma.sync.aligned.m16n8k8.row.col.f32.tf32.tf32.f32 "
        "{%0,%1,%2,%3}, {%4,%5,%6,%7}, {%8,%9}, {%0,%1,%2,%3};\n"
        : "+f"(d[0]), "+f"(d[1]), "+f"(d[2]), "+f"(d[3])
        : "r"(__float_as_uint(a[0])), "r"(__float_as_uint(a[1])),
          "r"(__float_as_uint(a[2])), "r"(__float_as_uint(a[3])),
          "r"(__float_as_uint(b0)),   "r"(__float_as_uint(b1)));
}

__device__ __forceinline__ float sigmoidf_(float x) {
    return 1.0f / (1.0f + __expf(-x));
}

// ------------------------- K/V projection kernel ---------------------------
// k[b,s,o] = dot(h_llm[b,s,:], Wk[o,:]) + bk[o] ; same for v.
// Block: 256 threads, handles 4 (b,s) rows. tid<128 -> k outputs, else v.
__global__ __launch_bounds__(256) void kv_kernel(
    const float* __restrict__ h_llm,
    const float* __restrict__ Wk, const float* __restrict__ bk,
    const float* __restrict__ Wv, const float* __restrict__ bv)
{
    __shared__ float hrows[4 * 2048];
    const int tid = threadIdx.x;
    const int bs0 = blockIdx.x * 4;     // grid = 128

    const float4* src = (const float4*)(h_llm + (size_t)bs0 * 2048);
    float4* dst = (float4*)hrows;
    for (int i = tid; i < 2048; i += 256) dst[i] = src[i];
    __syncthreads();

    const int o   = tid & 127;
    const bool isV = (tid >= 128);
    const float4* W = (const float4*)((isV ? Wv : Wk) + (size_t)o * 2048);
    const float4* h0 = (const float4*)hrows;
    const float4* h1 = h0 + 512;
    const float4* h2 = h0 + 1024;
    const float4* h3 = h0 + 1536;

    float4 a0 = make_float4(0,0,0,0), a1 = a0, a2 = a0, a3 = a0;
#pragma unroll 8
    for (int kk = 0; kk < 512; kk++) {
        const float4 w  = W[kk];
        const float4 x0 = h0[kk], x1 = h1[kk], x2 = h2[kk], x3 = h3[kk];
        a0.x += w.x*x0.x; a0.y += w.y*x0.y; a0.z += w.z*x0.z; a0.w += w.w*x0.w;
        a1.x += w.x*x1.x; a1.y += w.y*x1.y; a1.z += w.z*x1.z; a1.w += w.w*x1.w;
        a2.x += w.x*x2.x; a2.y += w.y*x2.y; a2.z += w.z*x2.z; a2.w += w.w*x2.w;
        a3.x += w.x*x3.x; a3.y += w.y*x3.y; a3.z += w.z*x3.z; a3.w += w.w*x3.w;
    }
    const float b = isV ? bv[o] : bk[o];
    float* outp = isV ? g_v : g_k;
    outp[(size_t)(bs0 + 0) * 128 + o] = a0.x + a0.y + a0.z + a0.w + b;
    outp[(size_t)(bs0 + 1) * 128 + o] = a1.x + a1.y + a1.z + a1.w + b;
    outp[(size_t)(bs0 + 2) * 128 + o] = a2.x + a2.y + a2.z + a2.w + b;
    outp[(size_t)(bs0 + 3) * 128 + o] = a3.x + a3.y + a3.z + a3.w + b;
}

// ----------------------------- maxpool kernel ------------------------------
// inv[tok,o] = max_g h_prime[tok, g*128 + o]
__global__ __launch_bounds__(256) void maxpool_kernel(const float* __restrict__ hp)
{
    const int tok = blockIdx.x * 2 + (threadIdx.x >> 7);   // grid = 16384
    const int o   = threadIdx.x & 127;
    const float* r = hp + (size_t)tok * 1024 + o;
    float m = r[0];
#pragma unroll
    for (int g = 1; g < 8; g++) m = fmaxf(m, r[g * 128]);
    g_inv[(size_t)tok * 128 + o] = m;
}

// ---------------- generic 128-K GEMM:  C = A[128r] * W^T + bias ------------
// Block tile 128x128x128, 8 warps in 4x2 layout, each warp 32x64.
// smem: As[128][132], Bs[128][132] (stride 132 -> conflict-free frag loads).
__device__ __forceinline__ void gemm128_bias(
    const float* __restrict__ A, const float* __restrict__ W,
    const float* __restrict__ bias, float* __restrict__ C)
{
    extern __shared__ float sm[];
    float* As = sm;
    float* Bs = sm + 128 * 132;
    const int tid  = threadIdx.x;
    const int lane = tid & 31, warp = tid >> 5;
    const int gid  = lane >> 2, qid = lane & 3;
    const int wm   = warp >> 1, wn  = warp & 1;
    const size_t m0 = (size_t)blockIdx.x * 128;

#pragma unroll
    for (int j = 0; j < 16; j++) {
        const int lin = j * 256 + tid;
        const int r = lin >> 5, c4 = (lin & 31) * 4;
        float4 va = *(const float4*)(A + (m0 + r) * 128 + c4);
        va.x = rna_tf32(va.x); va.y = rna_tf32(va.y);
        va.z = rna_tf32(va.z); va.w = rna_tf32(va.w);
        *(float4*)(As + r * 132 + c4) = va;
        float4 vb = *(const float4*)(W + (size_t)r * 128 + c4);
        vb.x = rna_tf32(vb.x); vb.y = rna_tf32(vb.y);
        vb.z = rna_tf32(vb.z); vb.w = rna_tf32(vb.w);
        *(float4*)(Bs + r * 132 + c4) = vb;
    }
    __syncthreads();

    float acc[2][8][4];
#pragma unroll
    for (int mt = 0; mt < 2; mt++)
#pragma unroll
        for (int nt = 0; nt < 8; nt++)
#pragma unroll
            for (int i = 0; i < 4; i++) acc[mt][nt][i] = 0.f;

#pragma unroll
    for (int k8 = 0; k8 < 16; k8++) {
        const int kb = k8 * 8;
        float a[2][4];
#pragma unroll
        for (int mt = 0; mt < 2; mt++) {
            const int r = wm * 32 + mt * 16 + gid;
            a[mt][0] = As[r * 132 + kb + qid];
            a[mt][1] = As[(r + 8) * 132 + kb + qid];
            a[mt][2] = As[r * 132 + kb + qid + 4];
            a[mt][3] = As[(r + 8) * 132 + kb + qid + 4];
        }
#pragma unroll
        for (int nt = 0; nt < 8; nt++) {
            const int c = wn * 64 + nt * 8 + gid;
            const float b0 = Bs[c * 132 + kb + qid];
            const float b1 = Bs[c * 132 + kb + qid + 4];
            mma_tf32(acc[0][nt], a[0], b0, b1);
            mma_tf32(acc[1][nt], a[1], b0, b1);
        }
    }

#pragma unroll
    for (int mt = 0; mt < 2; mt++)
#pragma unroll
        for (int nt = 0; nt < 8; nt++) {
            const size_t r = m0 + wm * 32 + mt * 16 + gid;
            const int c = wn * 64 + nt * 8 + qid * 2;
            const float b0 = bias[c], b1 = bias[c + 1];
            float2 o0 = make_float2(acc[mt][nt][0] + b0, acc[mt][nt][1] + b1);
            float2 o1 = make_float2(acc[mt][nt][2] + b0, acc[mt][nt][3] + b1);
            *(float2*)(C + r * 128 + c)       = o0;
            *(float2*)(C + (r + 8) * 128 + c) = o1;
        }
}

__global__ __launch_bounds__(256) void gemm_q_kernel(const float* __restrict__ Wq,
                                                     const float* __restrict__ bq)
{ gemm128_bias(g_inv, Wq, bq, g_q); }

__global__ __launch_bounds__(256) void gemm_gamma_kernel(const float* __restrict__ Wg,
                                                         const float* __restrict__ bg)
{ gemm128_bias(g_ctx, Wg, bg, g_gamma); }

__global__ __launch_bounds__(256) void gemm_beta_kernel(const float* __restrict__ Wb,
                                                        const float* __restrict__ bb)
{ gemm128_bias(g_ctx, Wb, bb, g_beta); }

// ----------------------------- attention kernel ----------------------------
// Per block: 16 tokens of one batch. scores = q.k * SCALE, softmax over 64,
// ctx = P @ v, gate = sigmoid(ctx). Block 256 thr = 16 tokens x 16 threads.
__global__ __launch_bounds__(256) void attn_kernel()
{
    extern __shared__ float sm[];
    float* qs = sm;                 // 16*128
    float* ks = sm + 2048;          // 64*128
    float* vs = ks + 8192;          // 64*128
    float* sc = vs + 8192;          // 16*64

    const int tid = threadIdx.x;
    const size_t tok0 = (size_t)blockIdx.x * 16;   // grid = 2048
    const int b = (int)(tok0 >> 12);               // 4096 tokens per batch

    const float4* kg = (const float4*)(g_k + (size_t)b * 64 * 128);
    const float4* vg = (const float4*)(g_v + (size_t)b * 64 * 128);
    const float4* qg = (const float4*)(g_q + tok0 * 128);
    for (int i = tid; i < 2048; i += 256) { ((float4*)ks)[i] = kg[i]; ((float4*)vs)[i] = vg[i]; }
    for (int i = tid; i < 512; i += 256) ((float4*)qs)[i] = qg[i];
    __syncthreads();

    const int lt  = tid >> 4;    // local token 0..15
    const int t16 = tid & 15;

    // scores (each thread: 4 keys)
    float raw[4];
#pragma unroll
    for (int j = 0; j < 4; j++) {
        const int s = t16 + j * 16;
        float acc = 0.f;
#pragma unroll
        for (int kk = 0; kk < 32; kk++) {
            const float4 q4 = ((const float4*)qs)[lt * 32 + kk];
            const float4 k4 = ((const float4*)ks)[s * 32 + kk];
            acc += q4.x * k4.x + q4.y * k4.y + q4.z * k4.z + q4.w * k4.w;
        }
        raw[j] = acc * SCALE_F;
        sc[lt * 64 + s] = raw[j];
    }
    __syncthreads();

    float m = -1e30f;
#pragma unroll
    for (int s = 0; s < 64; s++) m = fmaxf(m, sc[lt * 64 + s]);
    __syncthreads();
#pragma unroll
    for (int j = 0; j < 4; j++) sc[lt * 64 + t16 + j * 16] = __expf(raw[j] - m);
    __syncthreads();
    float sum = 0.f;
#pragma unroll
    for (int s = 0; s < 64; s++) sum += sc[lt * 64 + s];
    const float rs = 1.f / sum;

    float av[8] = {0,0,0,0,0,0,0,0};
    const float4* vs4 = (const float4*)vs;
#pragma unroll 8
    for (int s = 0; s < 64; s++) {
        const float p = sc[lt * 64 + s];
        const float4 v0 = vs4[s * 32 + t16 * 2];
        const float4 v1 = vs4[s * 32 + t16 * 2 + 1];
        av[0] += p * v0.x; av[1] += p * v0.y; av[2] += p * v0.z; av[3] += p * v0.w;
        av[4] += p * v1.x; av[5] += p * v1.y; av[6] += p * v1.z; av[7] += p * v1.w;
    }
    const size_t tok = tok0 + lt;
    float* cp = g_ctx  + tok * 128 + t16 * 8;
    float* gp = g_gate + tok * 128 + t16 * 8;
    float4 c0, c1, gg0, gg1;
    c0.x = av[0]*rs; c0.y = av[1]*rs; c0.z = av[2]*rs; c0.w = av[3]*rs;
    c1.x = av[4]*rs; c1.y = av[5]*rs; c1.z = av[6]*rs; c1.w = av[7]*rs;
    gg0.x = sigmoidf_(c0.x); gg0.y = sigmoidf_(c0.y); gg0.z = sigmoidf_(c0.z); gg0.w = sigmoidf_(c0.w);
    gg1.x = sigmoidf_(c1.x); gg1.y = sigmoidf_(c1.y); gg1.z = sigmoidf_(c1.z); gg1.w = sigmoidf_(c1.w);
    *(float4*)cp       = c0; *(float4*)(cp + 4) = c1;
    *(float4*)gp       = gg0; *(float4*)(gp + 4) = gg1;
}

// ---------------------- equi GEMM + modulation + residual ------------------
// rows = (b,n,t,g) -> M = 262144; out = h + gate*(gamma*(We@h_g) + beta).
// A tile is kept UNROUNDED in smem (needed for residual); tf32 rounding is
// applied per-fragment in registers.
__global__ __launch_bounds__(256) void gemm_equi_kernel(
    const float* __restrict__ Hp, const float* __restrict__ We,
    float* __restrict__ Out)
{
    extern __shared__ float sm[];
    float* As = sm;
    float* Bs = sm + 128 * 132;
    const int tid  = threadIdx.x;
    const int lane = tid & 31, warp = tid >> 5;
    const int gid  = lane >> 2, qid = lane & 3;
    const int wm   = warp >> 1, wn  = warp & 1;
    const size_t m0 = (size_t)blockIdx.x * 128;   // grid = 2048

#pragma unroll
    for (int j = 0; j < 16; j++) {
        const int lin = j * 256 + tid;
        const int r = lin >> 5, c4 = (lin & 31) * 4;
        *(float4*)(As + r * 132 + c4) = *(const float4*)(Hp + (m0 + r) * 128 + c4);
        float4 vb = *(const float4*)(We + (size_t)r * 128 + c4);
        vb.x = rna_tf32(vb.x); vb.y = rna_tf32(vb.y);
        vb.z = rna_tf32(vb.z); vb.w = rna_tf32(vb.w);
        *(float4*)(Bs + r * 132 + c4) = vb;
    }
    __syncthreads();

    float acc[2][8][4];
#pragma unroll
    for (int mt = 0; mt < 2; mt++)
#pragma unroll
        for (int nt = 0; nt < 8; nt++)
#pragma unroll
            for (int i = 0; i < 4; i++) acc[mt][nt][i] = 0.f;

#pragma unroll
    for (int k8 = 0; k8 < 16; k8++) {
        const int kb = k8 * 8;
        float a[2][4];
#pragma unroll
        for (int mt = 0; mt < 2; mt++) {
            const int r = wm * 32 + mt * 16 + gid;
            a[mt][0] = rna_tf32(As[r * 132 + kb + qid]);
            a[mt][1] = rna_tf32(As[(r + 8) * 132 + kb + qid]);
            a[mt][2] = rna_tf32(As[r * 132 + kb + qid + 4]);
            a[mt][3] = rna_tf32(As[(r + 8) * 132 + kb + qid + 4]);
        }
#pragma unroll
        for (int nt = 0; nt < 8; nt++) {
            const int c = wn * 64 + nt * 8 + gid;
            const float b0 = Bs[c * 132 + kb + qid];
            const float b1 = Bs[c * 132 + kb + qid + 4];
            mma_tf32(acc[0][nt], a[0], b0, b1);
            mma_tf32(acc[1][nt], a[1], b0, b1);
        }
    }

#pragma unroll
    for (int mt = 0; mt < 2; mt++)
#pragma unroll
        for (int nt = 0; nt < 8; nt++) {
            const int lr = wm * 32 + mt * 16 + gid;
            const int c  = wn * 64 + nt * 8 + qid * 2;
            const size_t grow = m0 + lr;
            {
                const size_t tok = grow >> 3;
                const float2 gt = *(const float2*)(g_gate  + tok * 128 + c);
                const float2 gm = *(const float2*)(g_gamma + tok * 128 + c);
                const float2 bt = *(const float2*)(g_beta  + tok * 128 + c);
                float2 o;
                o.x = As[lr * 132 + c]     + gt.x * (gm.x * acc[mt][nt][0] + bt.x);
                o.y = As[lr * 132 + c + 1] + gt.y * (gm.y * acc[mt][nt][1] + bt.y);
                *(float2*)(Out + grow * 128 + c) = o;
            }
            {
                const size_t grow2 = grow + 8;
                const size_t tok2 = grow2 >> 3;
                const float2 gt = *(const float2*)(g_gate  + tok2 * 128 + c);
                const float2 gm = *(const float2*)(g_gamma + tok2 * 128 + c);
                const float2 bt = *(const float2*)(g_beta  + tok2 * 128 + c);
                float2 o;
                o.x = As[(lr + 8) * 132 + c]     + gt.x * (gm.x * acc[mt][nt][2] + bt.x);
                o.y = As[(lr + 8) * 132 + c + 1] + gt.y * (gm.y * acc[mt][nt][3] + bt.y);
                *(float2*)(Out + grow2 * 128 + c) = o;
            }
        }
}

// ------------------------------- launcher ----------------------------------
extern "C" void kernel_launch(void* const* d_in, const int* in_sizes, int n_in,
                              void* d_out, int out_size)
{
    const float* h_prime = (const float*)d_in[0];
    const float* h_llm   = (const float*)d_in[1];
    const float* Wq = (const float*)d_in[2];
    const float* bq = (const float*)d_in[3];
    const float* Wk = (const float*)d_in[4];
    const float* bk = (const float*)d_in[5];
    const float* Wv = (const float*)d_in[6];
    const float* bv = (const float*)d_in[7];
    const float* Wg = (const float*)d_in[8];
    const float* bg = (const float*)d_in[9];
    const float* Wb = (const float*)d_in[10];
    const float* bb = (const float*)d_in[11];
    const float* We = (const float*)d_in[12];
    float* out = (float*)d_out;

    const int GEMM_SMEM = 2 * 128 * 132 * (int)sizeof(float);           // 135168
    const int ATTN_SMEM = (2048 + 8192 + 8192 + 1024) * (int)sizeof(float); // 77824

    cudaFuncSetAttribute(gemm_q_kernel,     cudaFuncAttributeMaxDynamicSharedMemorySize, GEMM_SMEM);
    cudaFuncSetAttribute(gemm_gamma_kernel, cudaFuncAttributeMaxDynamicSharedMemorySize, GEMM_SMEM);
    cudaFuncSetAttribute(gemm_beta_kernel,  cudaFuncAttributeMaxDynamicSharedMemorySize, GEMM_SMEM);
    cudaFuncSetAttribute(gemm_equi_kernel,  cudaFuncAttributeMaxDynamicSharedMemorySize, GEMM_SMEM);
    cudaFuncSetAttribute(attn_kernel,       cudaFuncAttributeMaxDynamicSharedMemorySize, ATTN_SMEM);

    kv_kernel<<<128, 256>>>(h_llm, Wk, bk, Wv, bv);
    maxpool_kernel<<<16384, 256>>>(h_prime);
    gemm_q_kernel<<<256, 256, GEMM_SMEM>>>(Wq, bq);
    attn_kernel<<<2048, 256, ATTN_SMEM>>>();
    gemm_gamma_kernel<<<256, 256, GEMM_SMEM>>>(Wg, bg);
    gemm_beta_kernel<<<256, 256, GEMM_SMEM>>>(Wb, bb);
    gemm_equi_kernel<<<2048, 256, GEMM_SMEM>>>(h_prime, We, out);
}

// round 3
// speedup vs baseline: 1.9562x; 1.9562x over previous
#include <cuda_runtime.h>
#include <cstdint>

// ---------------------------------------------------------------------------
// EquiAdapter, round 3: fully fused tensor-core pipeline.
// Shapes: B=8, n_equi=4, T=1024, D_eq=1024, N_GROUP=8, BLOCKS=128,
//         T_text=64, d_llm=2048.  NTOK = 32768 tokens, 262144 group-rows.
// Kernels:
//   1) kv_kernel   : k,v = h_llm @ {Wk,Wv}^T + bias           (small)
//   2) mid_kernel  : per 128-token tile, all on tf32 mma.sync:
//        maxpool -> q -> S=q.k^T -> softmax -> ctx=P.v -> gamma,beta
//        outputs gA = sigmoid(ctx)*gamma, gB = sigmoid(ctx)*beta
//   3) equi_kernel : out = h' + gA*(h_g @ We^T) + gB          (M-tile 64, 2 CTA/SM)
// ---------------------------------------------------------------------------

#define NTOK   32768
#define SCALE_F 0.08838834764831845f // 128^-0.5

__device__ float g_k[512 * 128];
__device__ float g_v[512 * 128];
__device__ float g_gA[NTOK * 128];   // gate * gamma
__device__ float g_gB[NTOK * 128];   // gate * beta

// ------------------------------ helpers ------------------------------------
__device__ __forceinline__ float rna_tf32(float x) {
    uint32_t r;
    asm("cvt.rna.tf32.f32 %0, %1;" : "=r"(r) : "f"(x));
    return __uint_as_float(r);
}
__device__ __forceinline__ float4 rna4(float4 v) {
    v.x = rna_tf32(v.x); v.y = rna_tf32(v.y);
    v.z = rna_tf32(v.z); v.w = rna_tf32(v.w);
    return v;
}
__device__ __forceinline__ void mma_tf32(float* d, const float* a, float b0, float b1) {
    asm volatile(
        "mma.sync.aligned.m16n8k8.row.col.f32.tf32.tf32.f32 "
        "{%0,%1,%2,%3}, {%4,%5,%6,%7}, {%8,%9}, {%0,%1,%2,%3};\n"
        : "+f"(d[0]), "+f"(d[1]), "+f"(d[2]), "+f"(d[3])
        : "r"(__float_as_uint(a[0])), "r"(__float_as_uint(a[1])),
          "r"(__float_as_uint(a[2])), "r"(__float_as_uint(a[3])),
          "r"(__float_as_uint(b0)),   "r"(__float_as_uint(b1)));
}
__device__ __forceinline__ float sigmoidf_(float x) {
    return 1.0f / (1.0f + __expf(-x));
}

// ------------------------- K/V projection kernel ---------------------------
__global__ __launch_bounds__(256) void kv_kernel(
    const float* __restrict__ h_llm,
    const float* __restrict__ Wk, const float* __restrict__ bk,
    const float* __restrict__ Wv, const float* __restrict__ bv)
{
    __shared__ float hrows[4 * 2048];
    const int tid = threadIdx.x;
    const int bs0 = blockIdx.x * 4;     // grid = 128

    const float4* src = (const float4*)(h_llm + (size_t)bs0 * 2048);
    float4* dst = (float4*)hrows;
    for (int i = tid; i < 2048; i += 256) dst[i] = src[i];
    __syncthreads();

    const int o   = tid & 127;
    const bool isV = (tid >= 128);
    const float4* W = (const float4*)((isV ? Wv : Wk) + (size_t)o * 2048);
    const float4* h0 = (const float4*)hrows;
    const float4* h1 = h0 + 512;
    const float4* h2 = h0 + 1024;
    const float4* h3 = h0 + 1536;

    float4 a0 = make_float4(0,0,0,0), a1 = a0, a2 = a0, a3 = a0;
#pragma unroll 8
    for (int kk = 0; kk < 512; kk++) {
        const float4 w  = W[kk];
        const float4 x0 = h0[kk], x1 = h1[kk], x2 = h2[kk], x3 = h3[kk];
        a0.x += w.x*x0.x; a0.y += w.y*x0.y; a0.z += w.z*x0.z; a0.w += w.w*x0.w;
        a1.x += w.x*x1.x; a1.y += w.y*x1.y; a1.z += w.z*x1.z; a1.w += w.w*x1.w;
        a2.x += w.x*x2.x; a2.y += w.y*x2.y; a2.z += w.z*x2.z; a2.w += w.w*x2.w;
        a3.x += w.x*x3.x; a3.y += w.y*x3.y; a3.z += w.z*x3.z; a3.w += w.w*x3.w;
    }
    const float b = isV ? bv[o] : bk[o];
    float* outp = isV ? g_v : g_k;
    outp[(size_t)(bs0 + 0) * 128 + o] = a0.x + a0.y + a0.z + a0.w + b;
    outp[(size_t)(bs0 + 1) * 128 + o] = a1.x + a1.y + a1.z + a1.w + b;
    outp[(size_t)(bs0 + 2) * 128 + o] = a2.x + a2.y + a2.z + a2.w + b;
    outp[(size_t)(bs0 + 3) * 128 + o] = a3.x + a3.y + a3.z + a3.w + b;
}

// --------------------------- fused mid kernel ------------------------------
// smem layout (floats):
//   A1 [128*132] : inv -> q -> ctx
//   WS [128*132] : Wq -> v^T -> Wg -> Wb
//   SS [128*68]  : k(64*132 fits) -> S/P
//   RS [128]     : per-row 1/sum
#define A1_OFF 0
#define WS_OFF 16896
#define SS_OFF 33792
#define RS_OFF (33792 + 8704)
#define MID_SMEM_FLOATS (33792 + 8704 + 128)

// 128x128xK mma over A(stride132) x B(stride132), 8 warps (4m x 2n), warp 32x64
__device__ __forceinline__ void mma_block_128(
    const float* __restrict__ As, const float* __restrict__ Bs,
    float acc[2][8][4], int wm, int wn, int gid, int qid, int kSteps, bool rndA)
{
#pragma unroll
    for (int k8 = 0; k8 < 16; k8++) {
        if (k8 >= kSteps) break;
        const int kb = k8 * 8;
        float a[2][4];
#pragma unroll
        for (int mt = 0; mt < 2; mt++) {
            const int r = wm * 32 + mt * 16 + gid;
            a[mt][0] = As[r * 132 + kb + qid];
            a[mt][1] = As[(r + 8) * 132 + kb + qid];
            a[mt][2] = As[r * 132 + kb + qid + 4];
            a[mt][3] = As[(r + 8) * 132 + kb + qid + 4];
            if (rndA) {
                a[mt][0] = rna_tf32(a[mt][0]); a[mt][1] = rna_tf32(a[mt][1]);
                a[mt][2] = rna_tf32(a[mt][2]); a[mt][3] = rna_tf32(a[mt][3]);
            }
        }
#pragma unroll
        for (int nt = 0; nt < 8; nt++) {
            const int c = wn * 64 + nt * 8 + gid;
            const float b0 = Bs[c * 132 + kb + qid];
            const float b1 = Bs[c * 132 + kb + qid + 4];
            mma_tf32(acc[0][nt], a[0], b0, b1);
            mma_tf32(acc[1][nt], a[1], b0, b1);
        }
    }
}

__global__ __launch_bounds__(256) void mid_kernel(
    const float* __restrict__ hp,
    const float* __restrict__ Wq, const float* __restrict__ bq,
    const float* __restrict__ Wg, const float* __restrict__ bg,
    const float* __restrict__ Wb, const float* __restrict__ bb)
{
    extern __shared__ float sm[];
    float* A1 = sm + A1_OFF;
    float* WS = sm + WS_OFF;
    float* SS = sm + SS_OFF;
    float* RS = sm + RS_OFF;

    const int tid = threadIdx.x;
    const int lane = tid & 31, warp = tid >> 5;
    const int gid = lane >> 2, qid = lane & 3;
    const int wm = warp >> 1, wn = warp & 1;
    const size_t tok0 = (size_t)blockIdx.x * 128;   // grid = 256
    const int b = (int)(tok0 >> 12);

    // ---- Phase A: maxpool -> A1 ; Wq -> WS ; k -> SS (all tf32-rounded) ----
#pragma unroll
    for (int i = 0; i < 16; i++) {
        const int t = i * 256 + tid;            // 4096 tasks
        const int r = t >> 5, c4 = (t & 31) << 2;
        const float* src = hp + (tok0 + r) * 1024 + c4;
        float4 m = *(const float4*)src;
#pragma unroll
        for (int g = 1; g < 8; g++) {
            const float4 x = *(const float4*)(src + g * 128);
            m.x = fmaxf(m.x, x.x); m.y = fmaxf(m.y, x.y);
            m.z = fmaxf(m.z, x.z); m.w = fmaxf(m.w, x.w);
        }
        *(float4*)(A1 + r * 132 + c4) = rna4(m);
        *(float4*)(WS + r * 132 + c4) = rna4(*(const float4*)(Wq + (size_t)r * 128 + c4));
    }
#pragma unroll
    for (int i = 0; i < 8; i++) {               // k: 64 rows x 32 float4
        const int t = i * 256 + tid;
        const int s = t >> 5, c4 = (t & 31) << 2;
        *(float4*)(SS + s * 132 + c4) = rna4(*(const float4*)(g_k + (size_t)b * 8192 + s * 128 + c4));
    }
    __syncthreads();

    float acc[2][8][4];

    // ---- Phase B: q = inv @ Wq^T + bq  (write back into A1) ----
#pragma unroll
    for (int mt = 0; mt < 2; mt++)
#pragma unroll
        for (int nt = 0; nt < 8; nt++)
#pragma unroll
            for (int i = 0; i < 4; i++) acc[mt][nt][i] = 0.f;
    mma_block_128(A1, WS, acc, wm, wn, gid, qid, 16, false);
    __syncthreads();   // all reads of A1(inv) done
#pragma unroll
    for (int mt = 0; mt < 2; mt++)
#pragma unroll
        for (int nt = 0; nt < 8; nt++) {
            const int r = wm * 32 + mt * 16 + gid;
            const int c = wn * 64 + nt * 8 + qid * 2;
            const float b0 = bq[c], b1 = bq[c + 1];
            A1[r * 132 + c]           = rna_tf32(acc[mt][nt][0] + b0);
            A1[r * 132 + c + 1]       = rna_tf32(acc[mt][nt][1] + b1);
            A1[(r + 8) * 132 + c]     = rna_tf32(acc[mt][nt][2] + b0);
            A1[(r + 8) * 132 + c + 1] = rna_tf32(acc[mt][nt][3] + b1);
        }
    __syncthreads();

    // ---- Phase C: S = q @ k^T  (N=64, warp 32x32) ----
    float acc4[2][4][4];
#pragma unroll
    for (int mt = 0; mt < 2; mt++)
#pragma unroll
        for (int nt = 0; nt < 4; nt++)
#pragma unroll
            for (int i = 0; i < 4; i++) acc4[mt][nt][i] = 0.f;
#pragma unroll
    for (int k8 = 0; k8 < 16; k8++) {
        const int kb = k8 * 8;
        float a[2][4];
#pragma unroll
        for (int mt = 0; mt < 2; mt++) {
            const int r = wm * 32 + mt * 16 + gid;
            a[mt][0] = A1[r * 132 + kb + qid];
            a[mt][1] = A1[(r + 8) * 132 + kb + qid];
            a[mt][2] = A1[r * 132 + kb + qid + 4];
            a[mt][3] = A1[(r + 8) * 132 + kb + qid + 4];
        }
#pragma unroll
        for (int nt = 0; nt < 4; nt++) {
            const int c = wn * 32 + nt * 8 + gid;
            const float b0 = SS[c * 132 + kb + qid];
            const float b1 = SS[c * 132 + kb + qid + 4];
            mma_tf32(acc4[0][nt], a[0], b0, b1);
            mma_tf32(acc4[1][nt], a[1], b0, b1);
        }
    }
    __syncthreads();   // all reads of SS(k) done
    // write S*SCALE into SS as [128][68]
#pragma unroll
    for (int mt = 0; mt < 2; mt++)
#pragma unroll
        for (int nt = 0; nt < 4; nt++) {
            const int r = wm * 32 + mt * 16 + gid;
            const int c = wn * 32 + nt * 8 + qid * 2;
            SS[r * 68 + c]           = acc4[mt][nt][0] * SCALE_F;
            SS[r * 68 + c + 1]       = acc4[mt][nt][1] * SCALE_F;
            SS[(r + 8) * 68 + c]     = acc4[mt][nt][2] * SCALE_F;
            SS[(r + 8) * 68 + c + 1] = acc4[mt][nt][3] * SCALE_F;
        }
    __syncthreads();

    // ---- softmax (unnormalized exp stored, 1/sum in RS) ----
    if (tid < 128) {
        const int row = tid;
        float m = -1e30f;
#pragma unroll
        for (int s = 0; s < 64; s++) m = fmaxf(m, SS[row * 68 + s]);
        float sum = 0.f;
#pragma unroll
        for (int s = 0; s < 64; s++) {
            const float e = rna_tf32(__expf(SS[row * 68 + s] - m));
            SS[row * 68 + s] = e;
            sum += e;
        }
        RS[row] = 1.f / sum;
    }
    __syncthreads();

    // ---- load v^T -> WS (tf32) ----
#pragma unroll
    for (int i = 0; i < 32; i++) {              // 8192 scalars
        const int t = i * 256 + tid;
        const int s = t >> 7, d = t & 127;
        WS[d * 132 + s] = rna_tf32(g_v[(size_t)b * 8192 + s * 128 + d]);
    }
    __syncthreads();

    // ---- Phase D: ctx = P @ v  (K=64, A from SS stride 68) -> A1 ----
#pragma unroll
    for (int mt = 0; mt < 2; mt++)
#pragma unroll
        for (int nt = 0; nt < 8; nt++)
#pragma unroll
            for (int i = 0; i < 4; i++) acc[mt][nt][i] = 0.f;
#pragma unroll
    for (int k8 = 0; k8 < 8; k8++) {
        const int kb = k8 * 8;
        float a[2][4];
#pragma unroll
        for (int mt = 0; mt < 2; mt++) {
            const int r = wm * 32 + mt * 16 + gid;
            a[mt][0] = SS[r * 68 + kb + qid];
            a[mt][1] = SS[(r + 8) * 68 + kb + qid];
            a[mt][2] = SS[r * 68 + kb + qid + 4];
            a[mt][3] = SS[(r + 8) * 68 + kb + qid + 4];
        }
#pragma unroll
        for (int nt = 0; nt < 8; nt++) {
            const int c = wn * 64 + nt * 8 + gid;
            const float b0 = WS[c * 132 + kb + qid];
            const float b1 = WS[c * 132 + kb + qid + 4];
            mma_tf32(acc[0][nt], a[0], b0, b1);
            mma_tf32(acc[1][nt], a[1], b0, b1);
        }
    }
    // ctx -> A1 (no one reads A1 during phase D)
#pragma unroll
    for (int mt = 0; mt < 2; mt++)
#pragma unroll
        for (int nt = 0; nt < 8; nt++) {
            const int r = wm * 32 + mt * 16 + gid;
            const int c = wn * 64 + nt * 8 + qid * 2;
            const float rs0 = RS[r], rs1 = RS[r + 8];
            A1[r * 132 + c]           = acc[mt][nt][0] * rs0;
            A1[r * 132 + c + 1]       = acc[mt][nt][1] * rs0;
            A1[(r + 8) * 132 + c]     = acc[mt][nt][2] * rs1;
            A1[(r + 8) * 132 + c + 1] = acc[mt][nt][3] * rs1;
        }
    __syncthreads();

    // ---- Phase F1: gamma -> g_gA = sigmoid(ctx) * (ctx@Wg^T + bg) ----
#pragma unroll
    for (int i = 0; i < 16; i++) {
        const int t = i * 256 + tid;
        const int r = t >> 5, c4 = (t & 31) << 2;
        *(float4*)(WS + r * 132 + c4) = rna4(*(const float4*)(Wg + (size_t)r * 128 + c4));
    }
    __syncthreads();
#pragma unroll
    for (int mt = 0; mt < 2; mt++)
#pragma unroll
        for (int nt = 0; nt < 8; nt++)
#pragma unroll
            for (int i = 0; i < 4; i++) acc[mt][nt][i] = 0.f;
    mma_block_128(A1, WS, acc, wm, wn, gid, qid, 16, true);
#pragma unroll
    for (int mt = 0; mt < 2; mt++)
#pragma unroll
        for (int nt = 0; nt < 8; nt++) {
            const int r = wm * 32 + mt * 16 + gid;
            const int c = wn * 64 + nt * 8 + qid * 2;
            const float b0 = bg[c], b1 = bg[c + 1];
            float2 o0, o1;
            o0.x = sigmoidf_(A1[r * 132 + c])           * (acc[mt][nt][0] + b0);
            o0.y = sigmoidf_(A1[r * 132 + c + 1])       * (acc[mt][nt][1] + b1);
            o1.x = sigmoidf_(A1[(r + 8) * 132 + c])     * (acc[mt][nt][2] + b0);
            o1.y = sigmoidf_(A1[(r + 8) * 132 + c + 1]) * (acc[mt][nt][3] + b1);
            *(float2*)(g_gA + (tok0 + r) * 128 + c)     = o0;
            *(float2*)(g_gA + (tok0 + r + 8) * 128 + c) = o1;
        }
    __syncthreads();

    // ---- Phase F2: beta -> g_gB ----
#pragma unroll
    for (int i = 0; i < 16; i++) {
        const int t = i * 256 + tid;
        const int r = t >> 5, c4 = (t & 31) << 2;
        *(float4*)(WS + r * 132 + c4) = rna4(*(const float4*)(Wb + (size_t)r * 128 + c4));
    }
    __syncthreads();
#pragma unroll
    for (int mt = 0; mt < 2; mt++)
#pragma unroll
        for (int nt = 0; nt < 8; nt++)
#pragma unroll
            for (int i = 0; i < 4; i++) acc[mt][nt][i] = 0.f;
    mma_block_128(A1, WS, acc, wm, wn, gid, qid, 16, true);
#pragma unroll
    for (int mt = 0; mt < 2; mt++)
#pragma unroll
        for (int nt = 0; nt < 8; nt++) {
            const int r = wm * 32 + mt * 16 + gid;
            const int c = wn * 64 + nt * 8 + qid * 2;
            const float b0 = bb[c], b1 = bb[c + 1];
            float2 o0, o1;
            o0.x = sigmoidf_(A1[r * 132 + c])           * (acc[mt][nt][0] + b0);
            o0.y = sigmoidf_(A1[r * 132 + c + 1])       * (acc[mt][nt][1] + b1);
            o1.x = sigmoidf_(A1[(r + 8) * 132 + c])     * (acc[mt][nt][2] + b0);
            o1.y = sigmoidf_(A1[(r + 8) * 132 + c + 1]) * (acc[mt][nt][3] + b1);
            *(float2*)(g_gB + (tok0 + r) * 128 + c)     = o0;
            *(float2*)(g_gB + (tok0 + r + 8) * 128 + c) = o1;
        }
}

// ---------------------- equi GEMM + modulation + residual ------------------
// M-tile 64 (rows are (tok,group) pairs), 8 warps (4m x 2n), warp 16x64.
// smem = 64*132 + 128*132 floats = 101.4 KB -> 2 CTAs/SM.
__global__ __launch_bounds__(256, 2) void equi_kernel(
    const float* __restrict__ Hp, const float* __restrict__ We,
    float* __restrict__ Out)
{
    extern __shared__ float sm[];
    float* As = sm;                 // 64*132, unrounded (residual)
    float* Bs = sm + 64 * 132;      // 128*132
    const int tid  = threadIdx.x;
    const int lane = tid & 31, warp = tid >> 5;
    const int gid  = lane >> 2, qid = lane & 3;
    const int wm   = warp >> 1, wn  = warp & 1;
    const size_t m0 = (size_t)blockIdx.x * 64;   // grid = 4096

#pragma unroll
    for (int i = 0; i < 8; i++) {
        const int t = i * 256 + tid;            // 2048 float4
        const int r = t >> 5, c4 = (t & 31) << 2;
        *(float4*)(As + r * 132 + c4) = *(const float4*)(Hp + (m0 + r) * 128 + c4);
    }
#pragma unroll
    for (int i = 0; i < 16; i++) {
        const int t = i * 256 + tid;            // 4096 float4
        const int r = t >> 5, c4 = (t & 31) << 2;
        *(float4*)(Bs + r * 132 + c4) = rna4(*(const float4*)(We + (size_t)r * 128 + c4));
    }
    __syncthreads();

    float acc[8][4];
#pragma unroll
    for (int nt = 0; nt < 8; nt++)
#pragma unroll
        for (int i = 0; i < 4; i++) acc[nt][i] = 0.f;

#pragma unroll
    for (int k8 = 0; k8 < 16; k8++) {
        const int kb = k8 * 8;
        const int r = wm * 16 + gid;
        float a[4];
        a[0] = rna_tf32(As[r * 132 + kb + qid]);
        a[1] = rna_tf32(As[(r + 8) * 132 + kb + qid]);
        a[2] = rna_tf32(As[r * 132 + kb + qid + 4]);
        a[3] = rna_tf32(As[(r + 8) * 132 + kb + qid + 4]);
#pragma unroll
        for (int nt = 0; nt < 8; nt++) {
            const int c = wn * 64 + nt * 8 + gid;
            const float b0 = Bs[c * 132 + kb + qid];
            const float b1 = Bs[c * 132 + kb + qid + 4];
            mma_tf32(acc[nt], a, b0, b1);
        }
    }

#pragma unroll
    for (int nt = 0; nt < 8; nt++) {
        const int lr = wm * 16 + gid;
        const int c  = wn * 64 + nt * 8 + qid * 2;
        {
            const size_t grow = m0 + lr;
            const size_t tok = grow >> 3;
            const float2 ga = *(const float2*)(g_gA + tok * 128 + c);
            const float2 gb = *(const float2*)(g_gB + tok * 128 + c);
            float2 o;
            o.x = As[lr * 132 + c]     + ga.x * acc[nt][0] + gb.x;
            o.y = As[lr * 132 + c + 1] + ga.y * acc[nt][1] + gb.y;
            *(float2*)(Out + grow * 128 + c) = o;
        }
        {
            const size_t grow = m0 + lr + 8;
            const size_t tok = grow >> 3;
            const float2 ga = *(const float2*)(g_gA + tok * 128 + c);
            const float2 gb = *(const float2*)(g_gB + tok * 128 + c);
            float2 o;
            o.x = As[(lr + 8) * 132 + c]     + ga.x * acc[nt][2] + gb.x;
            o.y = As[(lr + 8) * 132 + c + 1] + ga.y * acc[nt][3] + gb.y;
            *(float2*)(Out + grow * 128 + c) = o;
        }
    }
}

// ------------------------------- launcher ----------------------------------
extern "C" void kernel_launch(void* const* d_in, const int* in_sizes, int n_in,
                              void* d_out, int out_size)
{
    const float* h_prime = (const float*)d_in[0];
    const float* h_llm   = (const float*)d_in[1];
    const float* Wq = (const float*)d_in[2];
    const float* bq = (const float*)d_in[3];
    const float* Wk = (const float*)d_in[4];
    const float* bk = (const float*)d_in[5];
    const float* Wv = (const float*)d_in[6];
    const float* bv = (const float*)d_in[7];
    const float* Wg = (const float*)d_in[8];
    const float* bg = (const float*)d_in[9];
    const float* Wb = (const float*)d_in[10];
    const float* bb = (const float*)d_in[11];
    const float* We = (const float*)d_in[12];
    float* out = (float*)d_out;

    const int MID_SMEM  = MID_SMEM_FLOATS * (int)sizeof(float);          // 170496
    const int EQUI_SMEM = (64 * 132 + 128 * 132) * (int)sizeof(float);   // 101376

    cudaFuncSetAttribute(mid_kernel,  cudaFuncAttributeMaxDynamicSharedMemorySize, MID_SMEM);
    cudaFuncSetAttribute(equi_kernel, cudaFuncAttributeMaxDynamicSharedMemorySize, EQUI_SMEM);

    kv_kernel<<<128, 256>>>(h_llm, Wk, bk, Wv, bv);
    mid_kernel<<<256, 256, MID_SMEM>>>(h_prime, Wq, bq, Wg, bg, Wb, bb);
    equi_kernel<<<4096, 256, EQUI_SMEM>>>(h_prime, We, out);
}

// round 8
// speedup vs baseline: 2.5245x; 1.2905x over previous
#include <cuda_runtime.h>
#include <cstdint>

// ---------------------------------------------------------------------------
// EquiAdapter, round 4 design (resubmit x4 — broker timeouts, never ran).
//   1) kv_gemm_kernel : split-K tf32 GEMM  [512 x 256] = h_llm @ [Wk;Wv]^T
//   2) kv_reduce_kernel: sum 8 K-partials + bias -> g_k, g_v   (deterministic)
//   3) mid_kernel     : fused maxpool -> q -> attn -> gamma/beta
//   4) equi_kernel    : out = h' + gA*(h_g @ We^T) + gB  (2m x 4n warp layout)
// ---------------------------------------------------------------------------

#define NTOK   32768
#define SCALE_F 0.08838834764831845f // 128^-0.5

__device__ float g_k[512 * 128];
__device__ float g_v[512 * 128];
__device__ float g_part[8 * 512 * 256];   // split-K partials
__device__ float g_gA[NTOK * 128];        // gate * gamma
__device__ float g_gB[NTOK * 128];        // gate * beta

// ------------------------------ helpers ------------------------------------
__device__ __forceinline__ float rna_tf32(float x) {
    uint32_t r;
    asm("cvt.rna.tf32.f32 %0, %1;" : "=r"(r) : "f"(x));
    return __uint_as_float(r);
}
__device__ __forceinline__ float4 rna4(float4 v) {
    v.x = rna_tf32(v.x); v.y = rna_tf32(v.y);
    v.z = rna_tf32(v.z); v.w = rna_tf32(v.w);
    return v;
}
__device__ __forceinline__ void mma_tf32(float* d, const float* a, float b0, float b1) {
    asm volatile(
        "mma.sync.aligned.m16n8k8.row.col.f32.tf32.tf32.f32 "
        "{%0,%1,%2,%3}, {%4,%5,%6,%7}, {%8,%9}, {%0,%1,%2,%3};\n"
        : "+f"(d[0]), "+f"(d[1]), "+f"(d[2]), "+f"(d[3])
        : "r"(__float_as_uint(a[0])), "r"(__float_as_uint(a[1])),
          "r"(__float_as_uint(a[2])), "r"(__float_as_uint(a[3])),
          "r"(__float_as_uint(b0)),   "r"(__float_as_uint(b1)));
}
__device__ __forceinline__ float sigmoidf_(float x) {
    return 1.0f / (1.0f + __expf(-x));
}

// --------------------------- kv split-K GEMM -------------------------------
// grid: x in [0,32): mtile = x&7, ntile = x>>3 ;  y in [0,8): ksplit
// tile: M=64, N=64, K=256. smem stride 260 (260 mod 32 == 4 -> conflict-free).
__global__ __launch_bounds__(256) void kv_gemm_kernel(
    const float* __restrict__ h_llm,
    const float* __restrict__ Wk, const float* __restrict__ Wv)
{
    extern __shared__ float sm[];
    float* As = sm;                 // 64*260
    float* Bs = sm + 64 * 260;      // 64*260
    const int tid  = threadIdx.x;
    const int lane = tid & 31, warp = tid >> 5;
    const int gid  = lane >> 2, qid = lane & 3;
    const int wm   = warp >> 2, wn  = warp & 3;   // 2m x 4n, warp tile 32x16
    const int mtile = blockIdx.x & 7, ntile = blockIdx.x >> 3;
    const int s     = blockIdx.y;
    const int m0 = mtile * 64;
    const int n0 = ntile * 64;      // o' base in [0,256)
    const int k0 = s * 256;

#pragma unroll
    for (int i = 0; i < 16; i++) {
        const int t = i * 256 + tid;              // 4096 float4 tasks each
        const int r = t >> 6, c4 = (t & 63) << 2;
        *(float4*)(As + r * 260 + c4) =
            rna4(*(const float4*)(h_llm + (size_t)(m0 + r) * 2048 + k0 + c4));
        const int op = n0 + r;
        const float* Wrow = (op < 128) ? (Wk + (size_t)op * 2048)
                                       : (Wv + (size_t)(op - 128) * 2048);
        *(float4*)(Bs + r * 260 + c4) = rna4(*(const float4*)(Wrow + k0 + c4));
    }
    __syncthreads();

    float acc[2][2][4];
#pragma unroll
    for (int mt = 0; mt < 2; mt++)
#pragma unroll
        for (int nt = 0; nt < 2; nt++)
#pragma unroll
            for (int i = 0; i < 4; i++) acc[mt][nt][i] = 0.f;

#pragma unroll
    for (int k8 = 0; k8 < 32; k8++) {
        const int kb = k8 * 8;
        float a[2][4];
#pragma unroll
        for (int mt = 0; mt < 2; mt++) {
            const int r = wm * 32 + mt * 16 + gid;
            a[mt][0] = As[r * 260 + kb + qid];
            a[mt][1] = As[(r + 8) * 260 + kb + qid];
            a[mt][2] = As[r * 260 + kb + qid + 4];
            a[mt][3] = As[(r + 8) * 260 + kb + qid + 4];
        }
#pragma unroll
        for (int nt = 0; nt < 2; nt++) {
            const int c = wn * 16 + nt * 8 + gid;
            const float b0 = Bs[c * 260 + kb + qid];
            const float b1 = Bs[c * 260 + kb + qid + 4];
            mma_tf32(acc[0][nt], a[0], b0, b1);
            mma_tf32(acc[1][nt], a[1], b0, b1);
        }
    }

    float* part = g_part + (size_t)s * 512 * 256;
#pragma unroll
    for (int mt = 0; mt < 2; mt++)
#pragma unroll
        for (int nt = 0; nt < 2; nt++) {
            const int r = m0 + wm * 32 + mt * 16 + gid;
            const int c = n0 + wn * 16 + nt * 8 + qid * 2;
            *(float2*)(part + (size_t)r * 256 + c) =
                make_float2(acc[mt][nt][0], acc[mt][nt][1]);
            *(float2*)(part + (size_t)(r + 8) * 256 + c) =
                make_float2(acc[mt][nt][2], acc[mt][nt][3]);
        }
}

// ------------------------- kv reduce + bias --------------------------------
__global__ __launch_bounds__(256) void kv_reduce_kernel(
    const float* __restrict__ bk, const float* __restrict__ bv)
{
    const int idx = blockIdx.x * 256 + threadIdx.x;   // grid = 512 -> 131072
    const int row = idx >> 8, op = idx & 255;
    float sum = 0.f;
#pragma unroll
    for (int s = 0; s < 8; s++)
        sum += g_part[((size_t)s * 512 + row) * 256 + op];
    if (op < 128) g_k[(size_t)row * 128 + op]       = sum + bk[op];
    else          g_v[(size_t)row * 128 + op - 128] = sum + bv[op - 128];
}

// --------------------------- fused mid kernel ------------------------------
#define A1_OFF 0
#define WS_OFF 16896
#define SS_OFF 33792
#define RS_OFF (33792 + 8704)
#define MID_SMEM_FLOATS (33792 + 8704 + 128)

__device__ __forceinline__ void mma_block_128(
    const float* __restrict__ As, const float* __restrict__ Bs,
    float acc[2][8][4], int wm, int wn, int gid, int qid, int kSteps, bool rndA)
{
#pragma unroll
    for (int k8 = 0; k8 < 16; k8++) {
        if (k8 >= kSteps) break;
        const int kb = k8 * 8;
        float a[2][4];
#pragma unroll
        for (int mt = 0; mt < 2; mt++) {
            const int r = wm * 32 + mt * 16 + gid;
            a[mt][0] = As[r * 132 + kb + qid];
            a[mt][1] = As[(r + 8) * 132 + kb + qid];
            a[mt][2] = As[r * 132 + kb + qid + 4];
            a[mt][3] = As[(r + 8) * 132 + kb + qid + 4];
            if (rndA) {
                a[mt][0] = rna_tf32(a[mt][0]); a[mt][1] = rna_tf32(a[mt][1]);
                a[mt][2] = rna_tf32(a[mt][2]); a[mt][3] = rna_tf32(a[mt][3]);
            }
        }
#pragma unroll
        for (int nt = 0; nt < 8; nt++) {
            const int c = wn * 64 + nt * 8 + gid;
            const float b0 = Bs[c * 132 + kb + qid];
            const float b1 = Bs[c * 132 + kb + qid + 4];
            mma_tf32(acc[0][nt], a[0], b0, b1);
            mma_tf32(acc[1][nt], a[1], b0, b1);
        }
    }
}

__global__ __launch_bounds__(256) void mid_kernel(
    const float* __restrict__ hp,
    const float* __restrict__ Wq, const float* __restrict__ bq,
    const float* __restrict__ Wg, const float* __restrict__ bg,
    const float* __restrict__ Wb, const float* __restrict__ bb)
{
    extern __shared__ float sm[];
    float* A1 = sm + A1_OFF;
    float* WS = sm + WS_OFF;
    float* SS = sm + SS_OFF;
    float* RS = sm + RS_OFF;

    const int tid = threadIdx.x;
    const int lane = tid & 31, warp = tid >> 5;
    const int gid = lane >> 2, qid = lane & 3;
    const int wm = warp >> 1, wn = warp & 1;
    const size_t tok0 = (size_t)blockIdx.x * 128;   // grid = 256
    const int b = (int)(tok0 >> 12);

    // ---- Phase A: maxpool -> A1 ; Wq -> WS ; k -> SS ----
#pragma unroll
    for (int i = 0; i < 16; i++) {
        const int t = i * 256 + tid;
        const int r = t >> 5, c4 = (t & 31) << 2;
        const float* src = hp + (tok0 + r) * 1024 + c4;
        float4 m = *(const float4*)src;
#pragma unroll
        for (int g = 1; g < 8; g++) {
            const float4 x = *(const float4*)(src + g * 128);
            m.x = fmaxf(m.x, x.x); m.y = fmaxf(m.y, x.y);
            m.z = fmaxf(m.z, x.z); m.w = fmaxf(m.w, x.w);
        }
        *(float4*)(A1 + r * 132 + c4) = rna4(m);
        *(float4*)(WS + r * 132 + c4) = rna4(*(const float4*)(Wq + (size_t)r * 128 + c4));
    }
#pragma unroll
    for (int i = 0; i < 8; i++) {
        const int t = i * 256 + tid;
        const int s = t >> 5, c4 = (t & 31) << 2;
        *(float4*)(SS + s * 132 + c4) = rna4(*(const float4*)(g_k + (size_t)b * 8192 + s * 128 + c4));
    }
    __syncthreads();

    float acc[2][8][4];

    // ---- Phase B: q = inv @ Wq^T + bq ----
#pragma unroll
    for (int mt = 0; mt < 2; mt++)
#pragma unroll
        for (int nt = 0; nt < 8; nt++)
#pragma unroll
            for (int i = 0; i < 4; i++) acc[mt][nt][i] = 0.f;
    mma_block_128(A1, WS, acc, wm, wn, gid, qid, 16, false);
    __syncthreads();
#pragma unroll
    for (int mt = 0; mt < 2; mt++)
#pragma unroll
        for (int nt = 0; nt < 8; nt++) {
            const int r = wm * 32 + mt * 16 + gid;
            const int c = wn * 64 + nt * 8 + qid * 2;
            const float b0 = bq[c], b1 = bq[c + 1];
            A1[r * 132 + c]           = rna_tf32(acc[mt][nt][0] + b0);
            A1[r * 132 + c + 1]       = rna_tf32(acc[mt][nt][1] + b1);
            A1[(r + 8) * 132 + c]     = rna_tf32(acc[mt][nt][2] + b0);
            A1[(r + 8) * 132 + c + 1] = rna_tf32(acc[mt][nt][3] + b1);
        }
    __syncthreads();

    // ---- Phase C: S = q @ k^T ----
    float acc4[2][4][4];
#pragma unroll
    for (int mt = 0; mt < 2; mt++)
#pragma unroll
        for (int nt = 0; nt < 4; nt++)
#pragma unroll
            for (int i = 0; i < 4; i++) acc4[mt][nt][i] = 0.f;
#pragma unroll
    for (int k8 = 0; k8 < 16; k8++) {
        const int kb = k8 * 8;
        float a[2][4];
#pragma unroll
        for (int mt = 0; mt < 2; mt++) {
            const int r = wm * 32 + mt * 16 + gid;
            a[mt][0] = A1[r * 132 + kb + qid];
            a[mt][1] = A1[(r + 8) * 132 + kb + qid];
            a[mt][2] = A1[r * 132 + kb + qid + 4];
            a[mt][3] = A1[(r + 8) * 132 + kb + qid + 4];
        }
#pragma unroll
        for (int nt = 0; nt < 4; nt++) {
            const int c = wn * 32 + nt * 8 + gid;
            const float b0 = SS[c * 132 + kb + qid];
            const float b1 = SS[c * 132 + kb + qid + 4];
            mma_tf32(acc4[0][nt], a[0], b0, b1);
            mma_tf32(acc4[1][nt], a[1], b0, b1);
        }
    }
    __syncthreads();
#pragma unroll
    for (int mt = 0; mt < 2; mt++)
#pragma unroll
        for (int nt = 0; nt < 4; nt++) {
            const int r = wm * 32 + mt * 16 + gid;
            const int c = wn * 32 + nt * 8 + qid * 2;
            SS[r * 68 + c]           = acc4[mt][nt][0] * SCALE_F;
            SS[r * 68 + c + 1]       = acc4[mt][nt][1] * SCALE_F;
            SS[(r + 8) * 68 + c]     = acc4[mt][nt][2] * SCALE_F;
            SS[(r + 8) * 68 + c + 1] = acc4[mt][nt][3] * SCALE_F;
        }
    __syncthreads();

    // ---- softmax ----
    if (tid < 128) {
        const int row = tid;
        float m = -1e30f;
#pragma unroll
        for (int s = 0; s < 64; s++) m = fmaxf(m, SS[row * 68 + s]);
        float sum = 0.f;
#pragma unroll
        for (int s = 0; s < 64; s++) {
            const float e = rna_tf32(__expf(SS[row * 68 + s] - m));
            SS[row * 68 + s] = e;
            sum += e;
        }
        RS[row] = 1.f / sum;
    }
    __syncthreads();

    // ---- v^T -> WS ----
#pragma unroll
    for (int i = 0; i < 32; i++) {
        const int t = i * 256 + tid;
        const int s = t >> 7, d = t & 127;
        WS[d * 132 + s] = rna_tf32(g_v[(size_t)b * 8192 + s * 128 + d]);
    }
    __syncthreads();

    // ---- Phase D: ctx = P @ v -> A1 ----
#pragma unroll
    for (int mt = 0; mt < 2; mt++)
#pragma unroll
        for (int nt = 0; nt < 8; nt++)
#pragma unroll
            for (int i = 0; i < 4; i++) acc[mt][nt][i] = 0.f;
#pragma unroll
    for (int k8 = 0; k8 < 8; k8++) {
        const int kb = k8 * 8;
        float a[2][4];
#pragma unroll
        for (int mt = 0; mt < 2; mt++) {
            const int r = wm * 32 + mt * 16 + gid;
            a[mt][0] = SS[r * 68 + kb + qid];
            a[mt][1] = SS[(r + 8) * 68 + kb + qid];
            a[mt][2] = SS[r * 68 + kb + qid + 4];
            a[mt][3] = SS[(r + 8) * 68 + kb + qid + 4];
        }
#pragma unroll
        for (int nt = 0; nt < 8; nt++) {
            const int c = wn * 64 + nt * 8 + gid;
            const float b0 = WS[c * 132 + kb + qid];
            const float b1 = WS[c * 132 + kb + qid + 4];
            mma_tf32(acc[0][nt], a[0], b0, b1);
            mma_tf32(acc[1][nt], a[1], b0, b1);
        }
    }
#pragma unroll
    for (int mt = 0; mt < 2; mt++)
#pragma unroll
        for (int nt = 0; nt < 8; nt++) {
            const int r = wm * 32 + mt * 16 + gid;
            const int c = wn * 64 + nt * 8 + qid * 2;
            const float rs0 = RS[r], rs1 = RS[r + 8];
            A1[r * 132 + c]           = acc[mt][nt][0] * rs0;
            A1[r * 132 + c + 1]       = acc[mt][nt][1] * rs0;
            A1[(r + 8) * 132 + c]     = acc[mt][nt][2] * rs1;
            A1[(r + 8) * 132 + c + 1] = acc[mt][nt][3] * rs1;
        }
    __syncthreads();

    // ---- Phase F1: g_gA = sigmoid(ctx) * (ctx@Wg^T + bg) ----
#pragma unroll
    for (int i = 0; i < 16; i++) {
        const int t = i * 256 + tid;
        const int r = t >> 5, c4 = (t & 31) << 2;
        *(float4*)(WS + r * 132 + c4) = rna4(*(const float4*)(Wg + (size_t)r * 128 + c4));
    }
    __syncthreads();
#pragma unroll
    for (int mt = 0; mt < 2; mt++)
#pragma unroll
        for (int nt = 0; nt < 8; nt++)
#pragma unroll
            for (int i = 0; i < 4; i++) acc[mt][nt][i] = 0.f;
    mma_block_128(A1, WS, acc, wm, wn, gid, qid, 16, true);
#pragma unroll
    for (int mt = 0; mt < 2; mt++)
#pragma unroll
        for (int nt = 0; nt < 8; nt++) {
            const int r = wm * 32 + mt * 16 + gid;
            const int c = wn * 64 + nt * 8 + qid * 2;
            const float b0 = bg[c], b1 = bg[c + 1];
            float2 o0, o1;
            o0.x = sigmoidf_(A1[r * 132 + c])           * (acc[mt][nt][0] + b0);
            o0.y = sigmoidf_(A1[r * 132 + c + 1])       * (acc[mt][nt][1] + b1);
            o1.x = sigmoidf_(A1[(r + 8) * 132 + c])     * (acc[mt][nt][2] + b0);
            o1.y = sigmoidf_(A1[(r + 8) * 132 + c + 1]) * (acc[mt][nt][3] + b1);
            *(float2*)(g_gA + (tok0 + r) * 128 + c)     = o0;
            *(float2*)(g_gA + (tok0 + r + 8) * 128 + c) = o1;
        }
    __syncthreads();

    // ---- Phase F2: g_gB ----
#pragma unroll
    for (int i = 0; i < 16; i++) {
        const int t = i * 256 + tid;
        const int r = t >> 5, c4 = (t & 31) << 2;
        *(float4*)(WS + r * 132 + c4) = rna4(*(const float4*)(Wb + (size_t)r * 128 + c4));
    }
    __syncthreads();
#pragma unroll
    for (int mt = 0; mt < 2; mt++)
#pragma unroll
        for (int nt = 0; nt < 8; nt++)
#pragma unroll
            for (int i = 0; i < 4; i++) acc[mt][nt][i] = 0.f;
    mma_block_128(A1, WS, acc, wm, wn, gid, qid, 16, true);
#pragma unroll
    for (int mt = 0; mt < 2; mt++)
#pragma unroll
        for (int nt = 0; nt < 8; nt++) {
            const int r = wm * 32 + mt * 16 + gid;
            const int c = wn * 64 + nt * 8 + qid * 2;
            const float b0 = bb[c], b1 = bb[c + 1];
            float2 o0, o1;
            o0.x = sigmoidf_(A1[r * 132 + c])           * (acc[mt][nt][0] + b0);
            o0.y = sigmoidf_(A1[r * 132 + c + 1])       * (acc[mt][nt][1] + b1);
            o1.x = sigmoidf_(A1[(r + 8) * 132 + c])     * (acc[mt][nt][2] + b0);
            o1.y = sigmoidf_(A1[(r + 8) * 132 + c + 1]) * (acc[mt][nt][3] + b1);
            *(float2*)(g_gB + (tok0 + r) * 128 + c)     = o0;
            *(float2*)(g_gB + (tok0 + r + 8) * 128 + c) = o1;
        }
}

// ---------------------- equi GEMM + modulation + residual ------------------
// M-tile 64, 8 warps as 2m x 4n (warp 32x32): b-frags reused across mt.
__global__ __launch_bounds__(256, 2) void equi_kernel(
    const float* __restrict__ Hp, const float* __restrict__ We,
    float* __restrict__ Out)
{
    extern __shared__ float sm[];
    float* As = sm;                 // 64*132, unrounded (residual)
    float* Bs = sm + 64 * 132;      // 128*132
    const int tid  = threadIdx.x;
    const int lane = tid & 31, warp = tid >> 5;
    const int gid  = lane >> 2, qid = lane & 3;
    const int wm   = warp >> 2, wn  = warp & 3;   // 2m x 4n
    const size_t m0 = (size_t)blockIdx.x * 64;    // grid = 4096

#pragma unroll
    for (int i = 0; i < 8; i++) {
        const int t = i * 256 + tid;
        const int r = t >> 5, c4 = (t & 31) << 2;
        *(float4*)(As + r * 132 + c4) = *(const float4*)(Hp + (m0 + r) * 128 + c4);
    }
#pragma unroll
    for (int i = 0; i < 16; i++) {
        const int t = i * 256 + tid;
        const int r = t >> 5, c4 = (t & 31) << 2;
        *(float4*)(Bs + r * 132 + c4) = rna4(*(const float4*)(We + (size_t)r * 128 + c4));
    }
    __syncthreads();

    float acc[2][4][4];
#pragma unroll
    for (int mt = 0; mt < 2; mt++)
#pragma unroll
        for (int nt = 0; nt < 4; nt++)
#pragma unroll
            for (int i = 0; i < 4; i++) acc[mt][nt][i] = 0.f;

#pragma unroll
    for (int k8 = 0; k8 < 16; k8++) {
        const int kb = k8 * 8;
        float a[2][4];
#pragma unroll
        for (int mt = 0; mt < 2; mt++) {
            const int r = wm * 32 + mt * 16 + gid;
            a[mt][0] = rna_tf32(As[r * 132 + kb + qid]);
            a[mt][1] = rna_tf32(As[(r + 8) * 132 + kb + qid]);
            a[mt][2] = rna_tf32(As[r * 132 + kb + qid + 4]);
            a[mt][3] = rna_tf32(As[(r + 8) * 132 + kb + qid + 4]);
        }
#pragma unroll
        for (int nt = 0; nt < 4; nt++) {
            const int c = wn * 32 + nt * 8 + gid;
            const float b0 = Bs[c * 132 + kb + qid];
            const float b1 = Bs[c * 132 + kb + qid + 4];
            mma_tf32(acc[0][nt], a[0], b0, b1);
            mma_tf32(acc[1][nt], a[1], b0, b1);
        }
    }

#pragma unroll
    for (int mt = 0; mt < 2; mt++)
#pragma unroll
        for (int nt = 0; nt < 4; nt++) {
            const int lr = wm * 32 + mt * 16 + gid;
            const int c  = wn * 32 + nt * 8 + qid * 2;
            {
                const size_t grow = m0 + lr;
                const size_t tok = grow >> 3;
                const float2 ga = *(const float2*)(g_gA + tok * 128 + c);
                const float2 gb = *(const float2*)(g_gB + tok * 128 + c);
                float2 o;
                o.x = As[lr * 132 + c]     + ga.x * acc[mt][nt][0] + gb.x;
                o.y = As[lr * 132 + c + 1] + ga.y * acc[mt][nt][1] + gb.y;
                *(float2*)(Out + grow * 128 + c) = o;
            }
            {
                const size_t grow = m0 + lr + 8;
                const size_t tok = grow >> 3;
                const float2 ga = *(const float2*)(g_gA + tok * 128 + c);
                const float2 gb = *(const float2*)(g_gB + tok * 128 + c);
                float2 o;
                o.x = As[(lr + 8) * 132 + c]     + ga.x * acc[mt][nt][2] + gb.x;
                o.y = As[(lr + 8) * 132 + c + 1] + ga.y * acc[mt][nt][3] + gb.y;
                *(float2*)(Out + grow * 128 + c) = o;
            }
        }
}

// ------------------------------- launcher ----------------------------------
extern "C" void kernel_launch(void* const* d_in, const int* in_sizes, int n_in,
                              void* d_out, int out_size)
{
    const float* h_prime = (const float*)d_in[0];
    const float* h_llm   = (const float*)d_in[1];
    const float* Wq = (const float*)d_in[2];
    const float* bq = (const float*)d_in[3];
    const float* Wk = (const float*)d_in[4];
    const float* bk = (const float*)d_in[5];
    const float* Wv = (const float*)d_in[6];
    const float* bv = (const float*)d_in[7];
    const float* Wg = (const float*)d_in[8];
    const float* bg = (const float*)d_in[9];
    const float* Wb = (const float*)d_in[10];
    const float* bb = (const float*)d_in[11];
    const float* We = (const float*)d_in[12];
    float* out = (float*)d_out;

    const int KV_SMEM   = 2 * 64 * 260 * (int)sizeof(float);             // 133120
    const int MID_SMEM  = MID_SMEM_FLOATS * (int)sizeof(float);          // 170496
    const int EQUI_SMEM = (64 * 132 + 128 * 132) * (int)sizeof(float);   // 101376

    cudaFuncSetAttribute(kv_gemm_kernel, cudaFuncAttributeMaxDynamicSharedMemorySize, KV_SMEM);
    cudaFuncSetAttribute(mid_kernel,  cudaFuncAttributeMaxDynamicSharedMemorySize, MID_SMEM);
    cudaFuncSetAttribute(equi_kernel, cudaFuncAttributeMaxDynamicSharedMemorySize, EQUI_SMEM);

    kv_gemm_kernel<<<dim3(32, 8), 256, KV_SMEM>>>(h_llm, Wk, Wv);
    kv_reduce_kernel<<<512, 256>>>(bk, bv);
    mid_kernel<<<256, 256, MID_SMEM>>>(h_prime, Wq, bq, Wg, bg, Wb, bb);
    equi_kernel<<<4096, 256, EQUI_SMEM>>>(h_prime, We, out);
}

// round 12
// speedup vs baseline: 3.8052x; 1.5073x over previous
#include <cuda_runtime.h>
#include <cstdint>

// ---------------------------------------------------------------------------
// EquiAdapter, round 9 design (resubmit x3 — broker timeouts, never ran).
//   1) kv_gemm_kernel  : split-K tf32 GEMM (verified R8)
//   2) kv_reduce_kernel: partials + bias
//   3) wperm_kernel    : pre-permute We into mma-fragment order (coalesced LDG)
//   4) mid_kernel      : 512 threads (16 warps, 4m x 4n)
//   5) equi_kernel     : B-fragments from global (L1-hot), smem=As only, 3 CTAs/SM
// ---------------------------------------------------------------------------

#define NTOK   32768
#define SCALE_F 0.08838834764831845f // 128^-0.5

__device__ float g_k[512 * 128];
__device__ float g_v[512 * 128];
__device__ float g_part[8 * 512 * 256];   // split-K partials
__device__ float g_gA[NTOK * 128];        // gate * gamma
__device__ float g_gB[NTOK * 128];        // gate * beta
__device__ float g_wperm[16 * 128 * 4 * 2]; // We in fragment order (tf32)

// ------------------------------ helpers ------------------------------------
__device__ __forceinline__ float rna_tf32(float x) {
    uint32_t r;
    asm("cvt.rna.tf32.f32 %0, %1;" : "=r"(r) : "f"(x));
    return __uint_as_float(r);
}
__device__ __forceinline__ float4 rna4(float4 v) {
    v.x = rna_tf32(v.x); v.y = rna_tf32(v.y);
    v.z = rna_tf32(v.z); v.w = rna_tf32(v.w);
    return v;
}
__device__ __forceinline__ void mma_tf32(float* d, const float* a, float b0, float b1) {
    asm volatile(
        "mma.sync.aligned.m16n8k8.row.col.f32.tf32.tf32.f32 "
        "{%0,%1,%2,%3}, {%4,%5,%6,%7}, {%8,%9}, {%0,%1,%2,%3};\n"
        : "+f"(d[0]), "+f"(d[1]), "+f"(d[2]), "+f"(d[3])
        : "r"(__float_as_uint(a[0])), "r"(__float_as_uint(a[1])),
          "r"(__float_as_uint(a[2])), "r"(__float_as_uint(a[3])),
          "r"(__float_as_uint(b0)),   "r"(__float_as_uint(b1)));
}
__device__ __forceinline__ float sigmoidf_(float x) {
    return 1.0f / (1.0f + __expf(-x));
}

// --------------------------- kv split-K GEMM (unchanged) -------------------
__global__ __launch_bounds__(256) void kv_gemm_kernel(
    const float* __restrict__ h_llm,
    const float* __restrict__ Wk, const float* __restrict__ Wv)
{
    extern __shared__ float sm[];
    float* As = sm;                 // 64*260
    float* Bs = sm + 64 * 260;      // 64*260
    const int tid  = threadIdx.x;
    const int lane = tid & 31, warp = tid >> 5;
    const int gid  = lane >> 2, qid = lane & 3;
    const int wm   = warp >> 2, wn  = warp & 3;   // 2m x 4n, warp tile 32x16
    const int mtile = blockIdx.x & 7, ntile = blockIdx.x >> 3;
    const int s     = blockIdx.y;
    const int m0 = mtile * 64;
    const int n0 = ntile * 64;
    const int k0 = s * 256;

#pragma unroll
    for (int i = 0; i < 16; i++) {
        const int t = i * 256 + tid;
        const int r = t >> 6, c4 = (t & 63) << 2;
        *(float4*)(As + r * 260 + c4) =
            rna4(*(const float4*)(h_llm + (size_t)(m0 + r) * 2048 + k0 + c4));
        const int op = n0 + r;
        const float* Wrow = (op < 128) ? (Wk + (size_t)op * 2048)
                                       : (Wv + (size_t)(op - 128) * 2048);
        *(float4*)(Bs + r * 260 + c4) = rna4(*(const float4*)(Wrow + k0 + c4));
    }
    __syncthreads();

    float acc[2][2][4];
#pragma unroll
    for (int mt = 0; mt < 2; mt++)
#pragma unroll
        for (int nt = 0; nt < 2; nt++)
#pragma unroll
            for (int i = 0; i < 4; i++) acc[mt][nt][i] = 0.f;

#pragma unroll
    for (int k8 = 0; k8 < 32; k8++) {
        const int kb = k8 * 8;
        float a[2][4];
#pragma unroll
        for (int mt = 0; mt < 2; mt++) {
            const int r = wm * 32 + mt * 16 + gid;
            a[mt][0] = As[r * 260 + kb + qid];
            a[mt][1] = As[(r + 8) * 260 + kb + qid];
            a[mt][2] = As[r * 260 + kb + qid + 4];
            a[mt][3] = As[(r + 8) * 260 + kb + qid + 4];
        }
#pragma unroll
        for (int nt = 0; nt < 2; nt++) {
            const int c = wn * 16 + nt * 8 + gid;
            const float b0 = Bs[c * 260 + kb + qid];
            const float b1 = Bs[c * 260 + kb + qid + 4];
            mma_tf32(acc[0][nt], a[0], b0, b1);
            mma_tf32(acc[1][nt], a[1], b0, b1);
        }
    }

    float* part = g_part + (size_t)s * 512 * 256;
#pragma unroll
    for (int mt = 0; mt < 2; mt++)
#pragma unroll
        for (int nt = 0; nt < 2; nt++) {
            const int r = m0 + wm * 32 + mt * 16 + gid;
            const int c = n0 + wn * 16 + nt * 8 + qid * 2;
            *(float2*)(part + (size_t)r * 256 + c) =
                make_float2(acc[mt][nt][0], acc[mt][nt][1]);
            *(float2*)(part + (size_t)(r + 8) * 256 + c) =
                make_float2(acc[mt][nt][2], acc[mt][nt][3]);
        }
}

// ------------------------- kv reduce + bias (unchanged) --------------------
__global__ __launch_bounds__(256) void kv_reduce_kernel(
    const float* __restrict__ bk, const float* __restrict__ bv)
{
    const int idx = blockIdx.x * 256 + threadIdx.x;
    const int row = idx >> 8, op = idx & 255;
    float sum = 0.f;
#pragma unroll
    for (int s = 0; s < 8; s++)
        sum += g_part[((size_t)s * 512 + row) * 256 + op];
    if (op < 128) g_k[(size_t)row * 128 + op]       = sum + bk[op];
    else          g_v[(size_t)row * 128 + op - 128] = sum + bv[op - 128];
}

// ----------------------- We fragment-order permute -------------------------
// g_wperm[((k8*128 + c)*4 + qid)*2 + {0,1}] = tf32(We[c][k8*8+qid]), tf32(We[c][k8*8+qid+4])
// A warp's b-fragment load (lane = gid*4+qid, c = base+gid) is lane-linear
// 8 bytes -> fully coalesced LDG.64 from an L1-resident 64 KB table.
__global__ __launch_bounds__(256) void wperm_kernel(const float* __restrict__ We)
{
    const int i = blockIdx.x * 256 + threadIdx.x;   // grid = 32 -> 8192 pairs
    const int k8 = i >> 9, rem = i & 511;
    const int c = rem >> 2, qid = rem & 3;
    const float v0 = rna_tf32(We[(size_t)c * 128 + k8 * 8 + qid]);
    const float v1 = rna_tf32(We[(size_t)c * 128 + k8 * 8 + qid + 4]);
    g_wperm[(size_t)i * 2]     = v0;
    g_wperm[(size_t)i * 2 + 1] = v1;
}

// --------------------------- fused mid kernel (512 thr) --------------------
#define A1_OFF 0
#define WS_OFF 16896
#define SS_OFF 33792
#define RS_OFF (33792 + 8704)
#define MID_SMEM_FLOATS (33792 + 8704 + 128)

// 128x128xK mma, 16 warps as 4m x 4n (warp 32x32)
__device__ __forceinline__ void mma_block_16w(
    const float* __restrict__ As, const float* __restrict__ Bs,
    float acc[2][4][4], int wm, int wn, int gid, int qid, int kSteps, bool rndA)
{
#pragma unroll
    for (int k8 = 0; k8 < 16; k8++) {
        if (k8 >= kSteps) break;
        const int kb = k8 * 8;
        float a[2][4];
#pragma unroll
        for (int mt = 0; mt < 2; mt++) {
            const int r = wm * 32 + mt * 16 + gid;
            a[mt][0] = As[r * 132 + kb + qid];
            a[mt][1] = As[(r + 8) * 132 + kb + qid];
            a[mt][2] = As[r * 132 + kb + qid + 4];
            a[mt][3] = As[(r + 8) * 132 + kb + qid + 4];
            if (rndA) {
                a[mt][0] = rna_tf32(a[mt][0]); a[mt][1] = rna_tf32(a[mt][1]);
                a[mt][2] = rna_tf32(a[mt][2]); a[mt][3] = rna_tf32(a[mt][3]);
            }
        }
#pragma unroll
        for (int nt = 0; nt < 4; nt++) {
            const int c = wn * 32 + nt * 8 + gid;
            const float b0 = Bs[c * 132 + kb + qid];
            const float b1 = Bs[c * 132 + kb + qid + 4];
            mma_tf32(acc[0][nt], a[0], b0, b1);
            mma_tf32(acc[1][nt], a[1], b0, b1);
        }
    }
}

__global__ __launch_bounds__(512) void mid_kernel(
    const float* __restrict__ hp,
    const float* __restrict__ Wq, const float* __restrict__ bq,
    const float* __restrict__ Wg, const float* __restrict__ bg,
    const float* __restrict__ Wb, const float* __restrict__ bb)
{
    extern __shared__ float sm[];
    float* A1 = sm + A1_OFF;
    float* WS = sm + WS_OFF;
    float* SS = sm + SS_OFF;
    float* RS = sm + RS_OFF;

    const int tid = threadIdx.x;
    const int lane = tid & 31, warp = tid >> 5;
    const int gid = lane >> 2, qid = lane & 3;
    const int wm = warp >> 2, wn = warp & 3;     // 4m x 4n
    const size_t tok0 = (size_t)blockIdx.x * 128;   // grid = 256
    const int b = (int)(tok0 >> 12);

    // ---- Phase A: maxpool -> A1 ; Wq -> WS ; k -> SS ----
#pragma unroll
    for (int i = 0; i < 8; i++) {
        const int t = i * 512 + tid;            // 4096 float4 tasks
        const int r = t >> 5, c4 = (t & 31) << 2;
        const float* src = hp + (tok0 + r) * 1024 + c4;
        float4 m = *(const float4*)src;
#pragma unroll
        for (int g = 1; g < 8; g++) {
            const float4 x = *(const float4*)(src + g * 128);
            m.x = fmaxf(m.x, x.x); m.y = fmaxf(m.y, x.y);
            m.z = fmaxf(m.z, x.z); m.w = fmaxf(m.w, x.w);
        }
        *(float4*)(A1 + r * 132 + c4) = rna4(m);
        *(float4*)(WS + r * 132 + c4) = rna4(*(const float4*)(Wq + (size_t)r * 128 + c4));
    }
#pragma unroll
    for (int i = 0; i < 4; i++) {               // k: 64 rows x 32 float4
        const int t = i * 512 + tid;
        const int s = t >> 5, c4 = (t & 31) << 2;
        *(float4*)(SS + s * 132 + c4) = rna4(*(const float4*)(g_k + (size_t)b * 8192 + s * 128 + c4));
    }
    __syncthreads();

    float acc[2][4][4];

    // ---- Phase B: q = inv @ Wq^T + bq ----
#pragma unroll
    for (int mt = 0; mt < 2; mt++)
#pragma unroll
        for (int nt = 0; nt < 4; nt++)
#pragma unroll
            for (int i = 0; i < 4; i++) acc[mt][nt][i] = 0.f;
    mma_block_16w(A1, WS, acc, wm, wn, gid, qid, 16, false);
    __syncthreads();
#pragma unroll
    for (int mt = 0; mt < 2; mt++)
#pragma unroll
        for (int nt = 0; nt < 4; nt++) {
            const int r = wm * 32 + mt * 16 + gid;
            const int c = wn * 32 + nt * 8 + qid * 2;
            const float b0 = bq[c], b1 = bq[c + 1];
            A1[r * 132 + c]           = rna_tf32(acc[mt][nt][0] + b0);
            A1[r * 132 + c + 1]       = rna_tf32(acc[mt][nt][1] + b1);
            A1[(r + 8) * 132 + c]     = rna_tf32(acc[mt][nt][2] + b0);
            A1[(r + 8) * 132 + c + 1] = rna_tf32(acc[mt][nt][3] + b1);
        }
    __syncthreads();

    // ---- Phase C: S = q @ k^T (N=64, warp 32x16) ----
    float acc2[2][2][4];
#pragma unroll
    for (int mt = 0; mt < 2; mt++)
#pragma unroll
        for (int nt = 0; nt < 2; nt++)
#pragma unroll
            for (int i = 0; i < 4; i++) acc2[mt][nt][i] = 0.f;
#pragma unroll
    for (int k8 = 0; k8 < 16; k8++) {
        const int kb = k8 * 8;
        float a[2][4];
#pragma unroll
        for (int mt = 0; mt < 2; mt++) {
            const int r = wm * 32 + mt * 16 + gid;
            a[mt][0] = A1[r * 132 + kb + qid];
            a[mt][1] = A1[(r + 8) * 132 + kb + qid];
            a[mt][2] = A1[r * 132 + kb + qid + 4];
            a[mt][3] = A1[(r + 8) * 132 + kb + qid + 4];
        }
#pragma unroll
        for (int nt = 0; nt < 2; nt++) {
            const int c = wn * 16 + nt * 8 + gid;
            const float b0 = SS[c * 132 + kb + qid];
            const float b1 = SS[c * 132 + kb + qid + 4];
            mma_tf32(acc2[0][nt], a[0], b0, b1);
            mma_tf32(acc2[1][nt], a[1], b0, b1);
        }
    }
    __syncthreads();
#pragma unroll
    for (int mt = 0; mt < 2; mt++)
#pragma unroll
        for (int nt = 0; nt < 2; nt++) {
            const int r = wm * 32 + mt * 16 + gid;
            const int c = wn * 16 + nt * 8 + qid * 2;
            SS[r * 68 + c]           = acc2[mt][nt][0] * SCALE_F;
            SS[r * 68 + c + 1]       = acc2[mt][nt][1] * SCALE_F;
            SS[(r + 8) * 68 + c]     = acc2[mt][nt][2] * SCALE_F;
            SS[(r + 8) * 68 + c + 1] = acc2[mt][nt][3] * SCALE_F;
        }
    __syncthreads();

    // ---- softmax ----
    if (tid < 128) {
        const int row = tid;
        float m = -1e30f;
#pragma unroll
        for (int s = 0; s < 64; s++) m = fmaxf(m, SS[row * 68 + s]);
        float sum = 0.f;
#pragma unroll
        for (int s = 0; s < 64; s++) {
            const float e = rna_tf32(__expf(SS[row * 68 + s] - m));
            SS[row * 68 + s] = e;
            sum += e;
        }
        RS[row] = 1.f / sum;
    }
    __syncthreads();

    // ---- v^T -> WS ----
#pragma unroll
    for (int i = 0; i < 16; i++) {              // 8192 scalars
        const int t = i * 512 + tid;
        const int s = t >> 7, d = t & 127;
        WS[d * 132 + s] = rna_tf32(g_v[(size_t)b * 8192 + s * 128 + d]);
    }
    __syncthreads();

    // ---- Phase D: ctx = P @ v (K=64) -> A1 ----
#pragma unroll
    for (int mt = 0; mt < 2; mt++)
#pragma unroll
        for (int nt = 0; nt < 4; nt++)
#pragma unroll
            for (int i = 0; i < 4; i++) acc[mt][nt][i] = 0.f;
#pragma unroll
    for (int k8 = 0; k8 < 8; k8++) {
        const int kb = k8 * 8;
        float a[2][4];
#pragma unroll
        for (int mt = 0; mt < 2; mt++) {
            const int r = wm * 32 + mt * 16 + gid;
            a[mt][0] = SS[r * 68 + kb + qid];
            a[mt][1] = SS[(r + 8) * 68 + kb + qid];
            a[mt][2] = SS[r * 68 + kb + qid + 4];
            a[mt][3] = SS[(r + 8) * 68 + kb + qid + 4];
        }
#pragma unroll
        for (int nt = 0; nt < 4; nt++) {
            const int c = wn * 32 + nt * 8 + gid;
            const float b0 = WS[c * 132 + kb + qid];
            const float b1 = WS[c * 132 + kb + qid + 4];
            mma_tf32(acc[0][nt], a[0], b0, b1);
            mma_tf32(acc[1][nt], a[1], b0, b1);
        }
    }
#pragma unroll
    for (int mt = 0; mt < 2; mt++)
#pragma unroll
        for (int nt = 0; nt < 4; nt++) {
            const int r = wm * 32 + mt * 16 + gid;
            const int c = wn * 32 + nt * 8 + qid * 2;
            const float rs0 = RS[r], rs1 = RS[r + 8];
            A1[r * 132 + c]           = acc[mt][nt][0] * rs0;
            A1[r * 132 + c + 1]       = acc[mt][nt][1] * rs0;
            A1[(r + 8) * 132 + c]     = acc[mt][nt][2] * rs1;
            A1[(r + 8) * 132 + c + 1] = acc[mt][nt][3] * rs1;
        }
    __syncthreads();

    // ---- Phase F1: g_gA = sigmoid(ctx) * (ctx@Wg^T + bg) ----
#pragma unroll
    for (int i = 0; i < 8; i++) {
        const int t = i * 512 + tid;
        const int r = t >> 5, c4 = (t & 31) << 2;
        *(float4*)(WS + r * 132 + c4) = rna4(*(const float4*)(Wg + (size_t)r * 128 + c4));
    }
    __syncthreads();
#pragma unroll
    for (int mt = 0; mt < 2; mt++)
#pragma unroll
        for (int nt = 0; nt < 4; nt++)
#pragma unroll
            for (int i = 0; i < 4; i++) acc[mt][nt][i] = 0.f;
    mma_block_16w(A1, WS, acc, wm, wn, gid, qid, 16, true);
#pragma unroll
    for (int mt = 0; mt < 2; mt++)
#pragma unroll
        for (int nt = 0; nt < 4; nt++) {
            const int r = wm * 32 + mt * 16 + gid;
            const int c = wn * 32 + nt * 8 + qid * 2;
            const float b0 = bg[c], b1 = bg[c + 1];
            float2 o0, o1;
            o0.x = sigmoidf_(A1[r * 132 + c])           * (acc[mt][nt][0] + b0);
            o0.y = sigmoidf_(A1[r * 132 + c + 1])       * (acc[mt][nt][1] + b1);
            o1.x = sigmoidf_(A1[(r + 8) * 132 + c])     * (acc[mt][nt][2] + b0);
            o1.y = sigmoidf_(A1[(r + 8) * 132 + c + 1]) * (acc[mt][nt][3] + b1);
            *(float2*)(g_gA + (tok0 + r) * 128 + c)     = o0;
            *(float2*)(g_gA + (tok0 + r + 8) * 128 + c) = o1;
        }
    __syncthreads();

    // ---- Phase F2: g_gB ----
#pragma unroll
    for (int i = 0; i < 8; i++) {
        const int t = i * 512 + tid;
        const int r = t >> 5, c4 = (t & 31) << 2;
        *(float4*)(WS + r * 132 + c4) = rna4(*(const float4*)(Wb + (size_t)r * 128 + c4));
    }
    __syncthreads();
#pragma unroll
    for (int mt = 0; mt < 2; mt++)
#pragma unroll
        for (int nt = 0; nt < 4; nt++)
#pragma unroll
            for (int i = 0; i < 4; i++) acc[mt][nt][i] = 0.f;
    mma_block_16w(A1, WS, acc, wm, wn, gid, qid, 16, true);
#pragma unroll
    for (int mt = 0; mt < 2; mt++)
#pragma unroll
        for (int nt = 0; nt < 4; nt++) {
            const int r = wm * 32 + mt * 16 + gid;
            const int c = wn * 32 + nt * 8 + qid * 2;
            const float b0 = bb[c], b1 = bb[c + 1];
            float2 o0, o1;
            o0.x = sigmoidf_(A1[r * 132 + c])           * (acc[mt][nt][0] + b0);
            o0.y = sigmoidf_(A1[r * 132 + c + 1])       * (acc[mt][nt][1] + b1);
            o1.x = sigmoidf_(A1[(r + 8) * 132 + c])     * (acc[mt][nt][2] + b0);
            o1.y = sigmoidf_(A1[(r + 8) * 132 + c + 1]) * (acc[mt][nt][3] + b1);
            *(float2*)(g_gB + (tok0 + r) * 128 + c)     = o0;
            *(float2*)(g_gB + (tok0 + r + 8) * 128 + c) = o1;
        }
}

// ---------------------- equi GEMM + modulation + residual ------------------
// M-tile 64, 8 warps 2m x 4n (warp 32x32). B-fragments come straight from
// g_wperm (coalesced LDG.64, L1-resident). smem = As only -> 3 CTAs/SM.
__global__ __launch_bounds__(256, 3) void equi_kernel(
    const float* __restrict__ Hp, float* __restrict__ Out)
{
    extern __shared__ float sm[];
    float* As = sm;                 // 64*132, unrounded (residual)
    const int tid  = threadIdx.x;
    const int lane = tid & 31, warp = tid >> 5;
    const int gid  = lane >> 2, qid = lane & 3;
    const int wm   = warp >> 2, wn  = warp & 3;   // 2m x 4n
    const size_t m0 = (size_t)blockIdx.x * 64;    // grid = 4096
    const float2* __restrict__ wp = (const float2*)g_wperm;

#pragma unroll
    for (int i = 0; i < 8; i++) {
        const int t = i * 256 + tid;            // 2048 float4
        const int r = t >> 5, c4 = (t & 31) << 2;
        *(float4*)(As + r * 132 + c4) = *(const float4*)(Hp + (m0 + r) * 128 + c4);
    }
    __syncthreads();

    float acc[2][4][4];
#pragma unroll
    for (int mt = 0; mt < 2; mt++)
#pragma unroll
        for (int nt = 0; nt < 4; nt++)
#pragma unroll
            for (int i = 0; i < 4; i++) acc[mt][nt][i] = 0.f;

#pragma unroll
    for (int k8 = 0; k8 < 16; k8++) {
        const int kb = k8 * 8;
        float a[2][4];
#pragma unroll
        for (int mt = 0; mt < 2; mt++) {
            const int r = wm * 32 + mt * 16 + gid;
            a[mt][0] = rna_tf32(As[r * 132 + kb + qid]);
            a[mt][1] = rna_tf32(As[(r + 8) * 132 + kb + qid]);
            a[mt][2] = rna_tf32(As[r * 132 + kb + qid + 4]);
            a[mt][3] = rna_tf32(As[(r + 8) * 132 + kb + qid + 4]);
        }
#pragma unroll
        for (int nt = 0; nt < 4; nt++) {
            const int c = wn * 32 + nt * 8 + gid;
            const float2 b2 = __ldg(&wp[(k8 * 128 + c) * 4 + qid]);
            mma_tf32(acc[0][nt], a[0], b2.x, b2.y);
            mma_tf32(acc[1][nt], a[1], b2.x, b2.y);
        }
    }

#pragma unroll
    for (int mt = 0; mt < 2; mt++)
#pragma unroll
        for (int nt = 0; nt < 4; nt++) {
            const int lr = wm * 32 + mt * 16 + gid;
            const int c  = wn * 32 + nt * 8 + qid * 2;
            {
                const size_t grow = m0 + lr;
                const size_t tok = grow >> 3;
                const float2 ga = *(const float2*)(g_gA + tok * 128 + c);
                const float2 gb = *(const float2*)(g_gB + tok * 128 + c);
                float2 o;
                o.x = As[lr * 132 + c]     + ga.x * acc[mt][nt][0] + gb.x;
                o.y = As[lr * 132 + c + 1] + ga.y * acc[mt][nt][1] + gb.y;
                *(float2*)(Out + grow * 128 + c) = o;
            }
            {
                const size_t grow = m0 + lr + 8;
                const size_t tok = grow >> 3;
                const float2 ga = *(const float2*)(g_gA + tok * 128 + c);
                const float2 gb = *(const float2*)(g_gB + tok * 128 + c);
                float2 o;
                o.x = As[(lr + 8) * 132 + c]     + ga.x * acc[mt][nt][2] + gb.x;
                o.y = As[(lr + 8) * 132 + c + 1] + ga.y * acc[mt][nt][3] + gb.y;
                *(float2*)(Out + grow * 128 + c) = o;
            }
        }
}

// ------------------------------- launcher ----------------------------------
extern "C" void kernel_launch(void* const* d_in, const int* in_sizes, int n_in,
                              void* d_out, int out_size)
{
    const float* h_prime = (const float*)d_in[0];
    const float* h_llm   = (const float*)d_in[1];
    const float* Wq = (const float*)d_in[2];
    const float* bq = (const float*)d_in[3];
    const float* Wk = (const float*)d_in[4];
    const float* bk = (const float*)d_in[5];
    const float* Wv = (const float*)d_in[6];
    const float* bv = (const float*)d_in[7];
    const float* Wg = (const float*)d_in[8];
    const float* bg = (const float*)d_in[9];
    const float* Wb = (const float*)d_in[10];
    const float* bb = (const float*)d_in[11];
    const float* We = (const float*)d_in[12];
    float* out = (float*)d_out;

    const int KV_SMEM   = 2 * 64 * 260 * (int)sizeof(float);             // 133120
    const int MID_SMEM  = MID_SMEM_FLOATS * (int)sizeof(float);          // 170496
    const int EQUI_SMEM = (64 * 132) * (int)sizeof(float);               // 33792

    cudaFuncSetAttribute(kv_gemm_kernel, cudaFuncAttributeMaxDynamicSharedMemorySize, KV_SMEM);
    cudaFuncSetAttribute(mid_kernel,  cudaFuncAttributeMaxDynamicSharedMemorySize, MID_SMEM);
    cudaFuncSetAttribute(equi_kernel, cudaFuncAttributeMaxDynamicSharedMemorySize, EQUI_SMEM);

    kv_gemm_kernel<<<dim3(32, 8), 256, KV_SMEM>>>(h_llm, Wk, Wv);
    kv_reduce_kernel<<<512, 256>>>(bk, bv);
    wperm_kernel<<<32, 256>>>(We);
    mid_kernel<<<256, 512, MID_SMEM>>>(h_prime, Wq, bq, Wg, bg, Wb, bb);
    equi_kernel<<<4096, 256, EQUI_SMEM>>>(h_prime, out);
}